// round 16
// baseline (speedup 1.0000x reference)
#include <cuda_runtime.h>
#include <cuda_fp16.h>
#include <cstdint>

#define TEXT_DIM  1024
#define IMAGE_DIM 2048
#define NUM_HEADS 8
#define HEAD_DIM  128
#define BATCH     16384

// ---------------- device scratch (no cudaMalloc allowed) ----------------
__device__ __half g_Qh[(size_t)BATCH * TEXT_DIM];
__device__ __half g_Kh[(size_t)BATCH * TEXT_DIM];
__device__ __half g_Vh[(size_t)BATCH * TEXT_DIM];
__device__ __half g_Xt[(size_t)BATCH * TEXT_DIM];
__device__ __half g_Xi[(size_t)BATCH * IMAGE_DIM];
__device__ __half g_Wq[(size_t)TEXT_DIM * TEXT_DIM];
__device__ __half g_Wk[(size_t)TEXT_DIM * IMAGE_DIM];
__device__ __half g_Wv[(size_t)TEXT_DIM * IMAGE_DIM];
__device__ unsigned int g_ticket;

// ---------------- helpers ----------------
__device__ __forceinline__ uint32_t smem_u32(const void* p) {
    uint32_t a;
    asm("{ .reg .u64 t; cvta.to.shared.u64 t, %1; cvt.u32.u64 %0, t; }" : "=r"(a) : "l"(p));
    return a;
}
__device__ __forceinline__ void cp_async16(uint32_t dst, const void* src) {
    asm volatile("cp.async.cg.shared.global [%0], [%1], 16;" :: "r"(dst), "l"(src) : "memory");
}
#define CP_COMMIT() asm volatile("cp.async.commit_group;" ::: "memory")
#define CP_WAIT(N)  asm volatile("cp.async.wait_group %0;" :: "n"(N) : "memory")

#define LDSM_X4(r0, r1, r2, r3, addr) \
    asm volatile("ldmatrix.sync.aligned.m8n8.x4.shared.b16 {%0,%1,%2,%3}, [%4];" \
        : "=r"(r0), "=r"(r1), "=r"(r2), "=r"(r3) : "r"(addr))

__device__ __forceinline__ void mma16816(float* c, const uint32_t* a, const uint32_t* b) {
    asm volatile(
        "mma.sync.aligned.m16n8k16.row.col.f32.f16.f16.f32 "
        "{%0,%1,%2,%3}, {%4,%5,%6,%7}, {%8,%9}, {%0,%1,%2,%3};"
        : "+f"(c[0]), "+f"(c[1]), "+f"(c[2]), "+f"(c[3])
        : "r"(a[0]), "r"(a[1]), "r"(a[2]), "r"(a[3]), "r"(b[0]), "r"(b[1]));
}

// ---------------- fp16 GEMM core (frozen from R8) ----------------
#define BM 128
#define BN 128
#define BKH 64
#define STAGES 3
#define A_BYTES    (BM * 128)
#define B_BYTES    (BN * 128)
#define STAGE_BYTES (A_BYTES + B_BYTES)
#define TILE_OFF   1024
#define GEMM_SMEM  (TILE_OFF + STAGES * STAGE_BYTES)   // 99328
#define NT 128
#define N_TILES    3072
#define N_KV_TILES 2048

__device__ __forceinline__ void load_stage(uint32_t smem_base, int s,
                                           const __half* __restrict__ A,
                                           const __half* __restrict__ B,
                                           int K, int m0, int n0, int kt, int tid) {
    const uint32_t a_t = smem_base + TILE_OFF + s * STAGE_BYTES;
    const uint32_t b_t = a_t + A_BYTES;
    const int koff = kt * BKH;
    #pragma unroll
    for (int i = 0; i < 8; i++) {
        const int idx = tid + i * NT;
        const int row = idx >> 3;
        const int c   = idx & 7;
        const uint32_t sw = (uint32_t)((c * 16) ^ ((row & 7) * 16));
        cp_async16(a_t + row * 128 + sw, A + (size_t)(m0 + row) * K + koff + c * 8);
    }
    #pragma unroll
    for (int i = 0; i < 8; i++) {
        const int idx = tid + i * NT;
        const int row = idx >> 3;
        const int c   = idx & 7;
        const uint32_t sw = (uint32_t)((c * 16) ^ ((row & 7) * 16));
        cp_async16(b_t + row * 128 + sw, B + (size_t)(n0 + row) * K + koff + c * 8);
    }
    CP_COMMIT();
}

__device__ __forceinline__ void gemm_body(const __half* __restrict__ A,
                                          const __half* __restrict__ B,
                                          const float* __restrict__ bias,
                                          __half* __restrict__ C, int K,
                                          char* smem, int m0, int n0)
{
    const uint32_t sb = smem_u32(smem);
    const int tid  = threadIdx.x;
    const int lane = tid & 31;
    const int warp = tid >> 5;
    const int warpM = (warp & 1) * 64;
    const int warpN = (warp >> 1) * 64;

    if (tid < BN) ((float*)smem)[tid] = bias[n0 + tid];

    float acc[4][8][4];
    #pragma unroll
    for (int i = 0; i < 4; i++)
        #pragma unroll
        for (int j = 0; j < 8; j++)
            #pragma unroll
            for (int v = 0; v < 4; v++) acc[i][j][v] = 0.f;

    const int a_r  = lane & 15;
    const int a_kb = (lane >> 4) * 16;
    const int b_n  = ((lane >> 4) & 1) * 8 + (lane & 7);
    const int b_kb = ((lane >> 3) & 1) * 16;
    const uint32_t swc = (uint32_t)((lane & 7) * 16);

    uint32_t a_row_off[4], b_row_off[4];
    #pragma unroll
    for (int mt = 0; mt < 4; mt++) a_row_off[mt] = (uint32_t)((warpM + mt * 16 + a_r) * 128);
    #pragma unroll
    for (int p = 0; p < 4; p++)   b_row_off[p]  = (uint32_t)((warpN + p * 16 + b_n) * 128);

    const int NK = K / BKH;

    uint32_t av[2][4][4], bv[2][4][4];

#define LOAD_FRAGS(BUF, S) do {                                                   \
    const uint32_t akx = (uint32_t)(((S) * 32 + a_kb)) ^ swc;                     \
    const uint32_t bkx = (uint32_t)(((S) * 32 + b_kb)) ^ swc;                     \
    _Pragma("unroll")                                                             \
    for (int mt = 0; mt < 4; mt++)                                                \
        LDSM_X4(av[BUF][mt][0], av[BUF][mt][1], av[BUF][mt][2], av[BUF][mt][3],   \
                a_t + a_row_off[mt] + akx);                                       \
    _Pragma("unroll")                                                             \
    for (int p = 0; p < 4; p++)                                                   \
        LDSM_X4(bv[BUF][p][0], bv[BUF][p][1], bv[BUF][p][2], bv[BUF][p][3],       \
                b_t + b_row_off[p] + bkx);                                        \
} while (0)

#define DO_MMAS(BUF) do {                                                         \
    _Pragma("unroll")                                                             \
    for (int p = 0; p < 4; p++)                                                   \
        _Pragma("unroll")                                                         \
        for (int mt = 0; mt < 4; mt++) {                                          \
            mma16816(acc[mt][2 * p],     av[BUF][mt], &bv[BUF][p][0]);            \
            mma16816(acc[mt][2 * p + 1], av[BUF][mt], &bv[BUF][p][2]);            \
        }                                                                         \
} while (0)

    #pragma unroll
    for (int s = 0; s < STAGES - 1; s++)
        load_stage(sb, s, A, B, K, m0, n0, s, tid);

    CP_WAIT(STAGES - 2);
    __syncthreads();
    uint32_t a_t = sb + TILE_OFF;
    uint32_t b_t = a_t + A_BYTES;
    LOAD_FRAGS(0, 0);

    for (int kt = 0; kt < NK; kt++) {
        const int pf = kt + STAGES - 1;
        if (pf < NK) load_stage(sb, pf % STAGES, A, B, K, m0, n0, pf, tid);

        LOAD_FRAGS(1, 1);
        DO_MMAS(0);
        LOAD_FRAGS(0, 2);
        DO_MMAS(1);
        LOAD_FRAGS(1, 3);
        DO_MMAS(0);

        if (kt + 1 < NK) {
            CP_WAIT(STAGES - 2);
            __syncthreads();
            const uint32_t t = sb + TILE_OFF + ((kt + 1) % STAGES) * STAGE_BYTES;
            a_t = t;
            b_t = t + A_BYTES;
            LOAD_FRAGS(0, 0);
        }
        DO_MMAS(1);
    }

    const float* bs = (const float*)smem;
    #pragma unroll
    for (int mt = 0; mt < 4; mt++) {
        const int m = m0 + warpM + mt * 16 + (lane >> 2);
        #pragma unroll
        for (int nt = 0; nt < 8; nt++) {
            const int n = warpN + nt * 8 + ((lane & 3) << 1);
            const float b0v = bs[n], b1v = bs[n + 1];
            __half* r0 = C + (size_t)m * TEXT_DIM + n0 + n;
            __half* r1 = C + (size_t)(m + 8) * TEXT_DIM + n0 + n;
            *(__half2*)r0 = __floats2half2_rn(acc[mt][nt][0] + b0v, acc[mt][nt][1] + b1v);
            *(__half2*)r1 = __floats2half2_rn(acc[mt][nt][2] + b0v, acc[mt][nt][3] + b1v);
        }
    }
#undef LOAD_FRAGS
#undef DO_MMAS
}

// Persistent GEMM: 296 CTAs (2/SM) pull tile ids from a global ticket.
// Tile id space identical to R10: [0,2048) KV interleaved, [2048,3072) Q.
#define N_TILES_X (TEXT_DIM / BN)     // 8
__global__ __launch_bounds__(NT, 2)
void gemm_fp16_persist(const __half* __restrict__ Xi,
                       const __half* __restrict__ Bk, const float* __restrict__ bk,
                       __half* __restrict__ Ck,
                       const __half* __restrict__ Bv, const float* __restrict__ bv,
                       __half* __restrict__ Cv,
                       const __half* __restrict__ Xt,
                       const __half* __restrict__ Bq, const float* __restrict__ bq,
                       __half* __restrict__ Cq)
{
    extern __shared__ char smem[];
    __shared__ unsigned int s_id;

    for (;;) {
        if (threadIdx.x == 0) s_id = atomicAdd(&g_ticket, 1u);
        __syncthreads();
        const unsigned int id = s_id;
        if (id >= N_TILES) return;

        const __half* A;
        const __half* B;
        const float* bias;
        __half* C;
        int K, m0, n0;

        if (id < N_KV_TILES) {
            const int proj = id & 1;
            n0 = ((id >> 1) & (N_TILES_X - 1)) * BN;
            m0 = (id >> 4) * BM;
            A = Xi; K = IMAGE_DIM;
            if (proj == 0) { B = Bk; bias = bk; C = Ck; }
            else           { B = Bv; bias = bv; C = Cv; }
        } else {
            const int qid = id - N_KV_TILES;
            n0 = (qid & (N_TILES_X - 1)) * BN;
            m0 = (qid >> 3) * BM;
            A = Xt; K = TEXT_DIM;
            B = Bq; bias = bq; C = Cq;
        }
        gemm_body(A, B, bias, C, K, smem, m0, n0);
        __syncthreads();   // protect smem (bias region, s_id) before next tile
    }
}

// ---------------- conversion: 8 floats/thread/iter, 16B stores ----------------
__device__ __forceinline__ void cvt8(const float4* __restrict__ in,
                                     uint4* __restrict__ out, int i)
{
    const float4 va = in[2 * i];
    const float4 vb = in[2 * i + 1];
    uint4 o;
    *(__half2*)&o.x = __floats2half2_rn(va.x, va.y);
    *(__half2*)&o.y = __floats2half2_rn(va.z, va.w);
    *(__half2*)&o.z = __floats2half2_rn(vb.x, vb.y);
    *(__half2*)&o.w = __floats2half2_rn(vb.z, vb.w);
    out[i] = o;
}

__global__ __launch_bounds__(256)
void f32_to_f16_all(const float* __restrict__ i0, __half* __restrict__ o0, int n8_0,
                    const float* __restrict__ i1, __half* __restrict__ o1, int n8_1,
                    const float* __restrict__ i2, __half* __restrict__ o2, int n8_2,
                    const float* __restrict__ i3, __half* __restrict__ o3, int n8_3,
                    const float* __restrict__ i4, __half* __restrict__ o4, int n8_4)
{
    const int stride = gridDim.x * 256;
    const int t0 = blockIdx.x * 256 + threadIdx.x;
    #pragma unroll 1
    for (int i = t0; i < n8_0; i += stride) cvt8((const float4*)i0, (uint4*)o0, i);
    #pragma unroll 1
    for (int i = t0; i < n8_1; i += stride) cvt8((const float4*)i1, (uint4*)o1, i);
    #pragma unroll 1
    for (int i = t0; i < n8_2; i += stride) cvt8((const float4*)i2, (uint4*)o2, i);
    #pragma unroll 1
    for (int i = t0; i < n8_3; i += stride) cvt8((const float4*)i3, (uint4*)o3, i);
    #pragma unroll 1
    for (int i = t0; i < n8_4; i += stride) cvt8((const float4*)i4, (uint4*)o4, i);
}

// ---------------- fused attention + residual + LayerNorm ----------------
// 1 row / 256 threads; K,V kept as __half2 in smem (halved crossbar traffic).
__global__ __launch_bounds__(256)
void attn_ln_kernel(const __half* __restrict__ Qf, const __half* __restrict__ Kf,
                    const __half* __restrict__ Vf, const __half* __restrict__ Xt,
                    const float* __restrict__ gamma, const float* __restrict__ beta,
                    float* __restrict__ out)
{
    __shared__ __half2 sK2[TEXT_DIM / 2];
    __shared__ __half2 sV2[TEXT_DIM / 2];
    __shared__ float   sX[TEXT_DIM];
    __shared__ float   red[8][2];
    __shared__ float   stats[2];

    const int tid  = threadIdx.x;
    const int lane = tid & 31;
    const int h    = tid >> 5;
    const size_t base = (size_t)blockIdx.x * TEXT_DIM;

    {
        const uint2 kv = *(const uint2*)(Kf + base + tid * 4);
        const uint2 vv = *(const uint2*)(Vf + base + tid * 4);
        *(uint2*)(sK2 + tid * 2) = kv;
        *(uint2*)(sV2 + tid * 2) = vv;
    }

    const __half2* qh2 = (const __half2*)(Qf + base + h * HEAD_DIM);
    const float2 q2a = __half22float2(qh2[lane]);
    const float2 q2b = __half22float2(qh2[lane + 32]);
    __syncthreads();

    float s[NUM_HEADS];
    #pragma unroll
    for (int g = 0; g < NUM_HEADS; g++) {
        const __half2* kg = sK2 + g * (HEAD_DIM / 2);
        const float2 k2a = __half22float2(kg[lane]);
        const float2 k2b = __half22float2(kg[lane + 32]);
        float p = q2a.x * k2a.x + q2a.y * k2a.y + q2b.x * k2b.x + q2b.y * k2b.y;
        #pragma unroll
        for (int off = 16; off > 0; off >>= 1)
            p += __shfl_xor_sync(0xffffffffu, p, off);
        s[g] = p * 0.08838834764831845f;
    }
    float mx = s[0];
    #pragma unroll
    for (int g = 1; g < NUM_HEADS; g++) mx = fmaxf(mx, s[g]);
    float sum = 0.f;
    #pragma unroll
    for (int g = 0; g < NUM_HEADS; g++) { s[g] = __expf(s[g] - mx); sum += s[g]; }
    const float isum = 1.f / sum;

    const __half2* trow2 = (const __half2*)(Xt + base + h * HEAD_DIM);
    #pragma unroll
    for (int j = 0; j < 2; j++) {
        const int idx = lane + 32 * j;
        float ax = 0.f, ay = 0.f;
        #pragma unroll
        for (int g = 0; g < NUM_HEADS; g++) {
            const float2 v2 = __half22float2(sV2[g * (HEAD_DIM / 2) + idx]);
            ax += s[g] * v2.x;
            ay += s[g] * v2.y;
        }
        const float2 r2 = __half22float2(trow2[idx]);
        float2 xv2;
        xv2.x = ax * isum + r2.x;
        xv2.y = ay * isum + r2.y;
        *(float2*)(sX + h * HEAD_DIM + 2 * idx) = xv2;
    }
    __syncthreads();

    const float4 xv = *(const float4*)(sX + tid * 4);
    float sm = xv.x + xv.y + xv.z + xv.w;
    float sq = xv.x * xv.x + xv.y * xv.y + xv.z * xv.z + xv.w * xv.w;
    #pragma unroll
    for (int off = 16; off > 0; off >>= 1) {
        sm += __shfl_xor_sync(0xffffffffu, sm, off);
        sq += __shfl_xor_sync(0xffffffffu, sq, off);
    }
    if (lane == 0) { red[h][0] = sm; red[h][1] = sq; }
    __syncthreads();
    if (tid == 0) {
        float S = 0.f, SQ = 0.f;
        #pragma unroll
        for (int w = 0; w < 8; w++) { S += red[w][0]; SQ += red[w][1]; }
        const float mu  = S * (1.f / TEXT_DIM);
        const float var = SQ * (1.f / TEXT_DIM) - mu * mu;
        stats[0] = mu;
        stats[1] = rsqrtf(var + 1e-5f);
    }
    __syncthreads();
    const float mu = stats[0], rstd = stats[1];

    const float4 gv = *(const float4*)(gamma + tid * 4);
    const float4 bv = *(const float4*)(beta  + tid * 4);
    float4 yv;
    yv.x = (xv.x - mu) * rstd * gv.x + bv.x;
    yv.y = (xv.y - mu) * rstd * gv.y + bv.y;
    yv.z = (xv.z - mu) * rstd * gv.z + bv.z;
    yv.w = (xv.w - mu) * rstd * gv.w + bv.w;
    *(float4*)(out + base + tid * 4) = yv;
}

// ---------------- launch (single stream) ----------------
extern "C" void kernel_launch(void* const* d_in, const int* in_sizes, int n_in,
                              void* d_out, int out_size)
{
    const float* text  = (const float*)d_in[0];
    const float* image = (const float*)d_in[1];
    const float* Wq    = (const float*)d_in[2];
    const float* bq    = (const float*)d_in[3];
    const float* Wk    = (const float*)d_in[4];
    const float* bk    = (const float*)d_in[5];
    const float* Wv    = (const float*)d_in[6];
    const float* bv    = (const float*)d_in[7];
    const float* gamma = (const float*)d_in[8];
    const float* beta  = (const float*)d_in[9];
    float* out = (float*)d_out;

    __half *Qh, *Kh, *Vh, *Xt, *Xi, *Wqh, *Wkh, *Wvh;
    unsigned int* ticket;
    cudaGetSymbolAddress((void**)&Qh,  g_Qh);
    cudaGetSymbolAddress((void**)&Kh,  g_Kh);
    cudaGetSymbolAddress((void**)&Vh,  g_Vh);
    cudaGetSymbolAddress((void**)&Xt,  g_Xt);
    cudaGetSymbolAddress((void**)&Xi,  g_Xi);
    cudaGetSymbolAddress((void**)&Wqh, g_Wq);
    cudaGetSymbolAddress((void**)&Wkh, g_Wk);
    cudaGetSymbolAddress((void**)&Wvh, g_Wv);
    cudaGetSymbolAddress((void**)&ticket, g_ticket);

    cudaFuncSetAttribute(gemm_fp16_persist,
                         cudaFuncAttributeMaxDynamicSharedMemorySize, GEMM_SMEM);

    {
        const int n8i = (BATCH * IMAGE_DIM) / 8;
        const int n8t = (BATCH * TEXT_DIM) / 8;
        const int n8k = (TEXT_DIM * IMAGE_DIM) / 8;
        const int n8q = (TEXT_DIM * TEXT_DIM) / 8;
        f32_to_f16_all<<<4096, 256>>>(image, Xi, n8i,
                                      text,  Xt, n8t,
                                      Wk,    Wkh, n8k,
                                      Wv,    Wvh, n8k,
                                      Wq,    Wqh, n8q);
    }

    cudaMemsetAsync(ticket, 0, sizeof(unsigned int), 0);
    gemm_fp16_persist<<<296, NT, GEMM_SMEM>>>(Xi, Wkh, bk, Kh, Wvh, bv, Vh,
                                              Xt, Wqh, bq, Qh);

    attn_ln_kernel<<<BATCH, 256>>>(Qh, Kh, Vh, Xt, gamma, beta, out);
}

// round 17
// speedup vs baseline: 1.1224x; 1.1224x over previous
#include <cuda_runtime.h>
#include <cuda_fp16.h>
#include <cstdint>

#define TEXT_DIM  1024
#define IMAGE_DIM 2048
#define NUM_HEADS 8
#define HEAD_DIM  128
#define BATCH     16384

// ---------------- device scratch (no cudaMalloc allowed) ----------------
__device__ __half g_Qh[(size_t)BATCH * TEXT_DIM];
__device__ __half g_Kh[(size_t)BATCH * TEXT_DIM];
__device__ __half g_Vh[(size_t)BATCH * TEXT_DIM];
__device__ __half g_Xt[(size_t)BATCH * TEXT_DIM];
__device__ __half g_Xi[(size_t)BATCH * IMAGE_DIM];
__device__ __half g_Wq[(size_t)TEXT_DIM * TEXT_DIM];
__device__ __half g_Wk[(size_t)TEXT_DIM * IMAGE_DIM];
__device__ __half g_Wv[(size_t)TEXT_DIM * IMAGE_DIM];

// ---------------- helpers ----------------
__device__ __forceinline__ uint32_t smem_u32(const void* p) {
    uint32_t a;
    asm("{ .reg .u64 t; cvta.to.shared.u64 t, %1; cvt.u32.u64 %0, t; }" : "=r"(a) : "l"(p));
    return a;
}
__device__ __forceinline__ void cp_async16(uint32_t dst, const void* src) {
    asm volatile("cp.async.cg.shared.global [%0], [%1], 16;" :: "r"(dst), "l"(src) : "memory");
}
#define CP_COMMIT() asm volatile("cp.async.commit_group;" ::: "memory")
#define CP_WAIT(N)  asm volatile("cp.async.wait_group %0;" :: "n"(N) : "memory")

#define LDSM_X4(r0, r1, r2, r3, addr) \
    asm volatile("ldmatrix.sync.aligned.m8n8.x4.shared.b16 {%0,%1,%2,%3}, [%4];" \
        : "=r"(r0), "=r"(r1), "=r"(r2), "=r"(r3) : "r"(addr))

__device__ __forceinline__ void mma16816(float* c, const uint32_t* a, const uint32_t* b) {
    asm volatile(
        "mma.sync.aligned.m16n8k16.row.col.f32.f16.f16.f32 "
        "{%0,%1,%2,%3}, {%4,%5,%6,%7}, {%8,%9}, {%0,%1,%2,%3};"
        : "+f"(c[0]), "+f"(c[1]), "+f"(c[2]), "+f"(c[3])
        : "r"(a[0]), "r"(a[1]), "r"(a[2]), "r"(a[3]), "r"(b[0]), "r"(b[1]));
}

// ---------------- fp16 GEMM core (frozen from R8) ----------------
#define BM 128
#define BN 128
#define BKH 64
#define STAGES 3
#define A_BYTES    (BM * 128)
#define B_BYTES    (BN * 128)
#define STAGE_BYTES (A_BYTES + B_BYTES)
#define TILE_OFF   1024
#define GEMM_SMEM  (TILE_OFF + STAGES * STAGE_BYTES)   // 99328
#define NT 128

__device__ __forceinline__ void load_stage(uint32_t smem_base, int s,
                                           const __half* __restrict__ A,
                                           const __half* __restrict__ B,
                                           int K, int m0, int n0, int kt, int tid) {
    const uint32_t a_t = smem_base + TILE_OFF + s * STAGE_BYTES;
    const uint32_t b_t = a_t + A_BYTES;
    const int koff = kt * BKH;
    #pragma unroll
    for (int i = 0; i < 8; i++) {
        const int idx = tid + i * NT;
        const int row = idx >> 3;
        const int c   = idx & 7;
        const uint32_t sw = (uint32_t)((c * 16) ^ ((row & 7) * 16));
        cp_async16(a_t + row * 128 + sw, A + (size_t)(m0 + row) * K + koff + c * 8);
    }
    #pragma unroll
    for (int i = 0; i < 8; i++) {
        const int idx = tid + i * NT;
        const int row = idx >> 3;
        const int c   = idx & 7;
        const uint32_t sw = (uint32_t)((c * 16) ^ ((row & 7) * 16));
        cp_async16(b_t + row * 128 + sw, B + (size_t)(n0 + row) * K + koff + c * 8);
    }
    CP_COMMIT();
}

__device__ __forceinline__ void gemm_body(const __half* __restrict__ A,
                                          const __half* __restrict__ B,
                                          const float* __restrict__ bias,
                                          __half* __restrict__ C, int K,
                                          char* smem, int m0, int n0)
{
    const uint32_t sb = smem_u32(smem);
    const int tid  = threadIdx.x;
    const int lane = tid & 31;
    const int warp = tid >> 5;
    const int warpM = (warp & 1) * 64;
    const int warpN = (warp >> 1) * 64;

    if (tid < BN) ((float*)smem)[tid] = bias[n0 + tid];

    float acc[4][8][4];
    #pragma unroll
    for (int i = 0; i < 4; i++)
        #pragma unroll
        for (int j = 0; j < 8; j++)
            #pragma unroll
            for (int v = 0; v < 4; v++) acc[i][j][v] = 0.f;

    const int a_r  = lane & 15;
    const int a_kb = (lane >> 4) * 16;
    const int b_n  = ((lane >> 4) & 1) * 8 + (lane & 7);
    const int b_kb = ((lane >> 3) & 1) * 16;
    const uint32_t swc = (uint32_t)((lane & 7) * 16);

    uint32_t a_row_off[4], b_row_off[4];
    #pragma unroll
    for (int mt = 0; mt < 4; mt++) a_row_off[mt] = (uint32_t)((warpM + mt * 16 + a_r) * 128);
    #pragma unroll
    for (int p = 0; p < 4; p++)   b_row_off[p]  = (uint32_t)((warpN + p * 16 + b_n) * 128);

    const int NK = K / BKH;

    uint32_t av[2][4][4], bv[2][4][4];

#define LOAD_FRAGS(BUF, S) do {                                                   \
    const uint32_t akx = (uint32_t)(((S) * 32 + a_kb)) ^ swc;                     \
    const uint32_t bkx = (uint32_t)(((S) * 32 + b_kb)) ^ swc;                     \
    _Pragma("unroll")                                                             \
    for (int mt = 0; mt < 4; mt++)                                                \
        LDSM_X4(av[BUF][mt][0], av[BUF][mt][1], av[BUF][mt][2], av[BUF][mt][3],   \
                a_t + a_row_off[mt] + akx);                                       \
    _Pragma("unroll")                                                             \
    for (int p = 0; p < 4; p++)                                                   \
        LDSM_X4(bv[BUF][p][0], bv[BUF][p][1], bv[BUF][p][2], bv[BUF][p][3],       \
                b_t + b_row_off[p] + bkx);                                        \
} while (0)

#define DO_MMAS(BUF) do {                                                         \
    _Pragma("unroll")                                                             \
    for (int p = 0; p < 4; p++)                                                   \
        _Pragma("unroll")                                                         \
        for (int mt = 0; mt < 4; mt++) {                                          \
            mma16816(acc[mt][2 * p],     av[BUF][mt], &bv[BUF][p][0]);            \
            mma16816(acc[mt][2 * p + 1], av[BUF][mt], &bv[BUF][p][2]);            \
        }                                                                         \
} while (0)

    #pragma unroll
    for (int s = 0; s < STAGES - 1; s++)
        load_stage(sb, s, A, B, K, m0, n0, s, tid);

    CP_WAIT(STAGES - 2);
    __syncthreads();
    uint32_t a_t = sb + TILE_OFF;
    uint32_t b_t = a_t + A_BYTES;
    LOAD_FRAGS(0, 0);

    for (int kt = 0; kt < NK; kt++) {
        const int pf = kt + STAGES - 1;
        if (pf < NK) load_stage(sb, pf % STAGES, A, B, K, m0, n0, pf, tid);

        LOAD_FRAGS(1, 1);
        DO_MMAS(0);
        LOAD_FRAGS(0, 2);
        DO_MMAS(1);
        LOAD_FRAGS(1, 3);
        DO_MMAS(0);

        if (kt + 1 < NK) {
            CP_WAIT(STAGES - 2);
            __syncthreads();
            const uint32_t t = sb + TILE_OFF + ((kt + 1) % STAGES) * STAGE_BYTES;
            a_t = t;
            b_t = t + A_BYTES;
            LOAD_FRAGS(0, 0);
        }
        DO_MMAS(1);
    }

    const float* bs = (const float*)smem;
    #pragma unroll
    for (int mt = 0; mt < 4; mt++) {
        const int m = m0 + warpM + mt * 16 + (lane >> 2);
        #pragma unroll
        for (int nt = 0; nt < 8; nt++) {
            const int n = warpN + nt * 8 + ((lane & 3) << 1);
            const float b0v = bs[n], b1v = bs[n + 1];
            __half* r0 = C + (size_t)m * TEXT_DIM + n0 + n;
            __half* r1 = C + (size_t)(m + 8) * TEXT_DIM + n0 + n;
            *(__half2*)r0 = __floats2half2_rn(acc[mt][nt][0] + b0v, acc[mt][nt][1] + b1v);
            *(__half2*)r1 = __floats2half2_rn(acc[mt][nt][2] + b0v, acc[mt][nt][3] + b1v);
        }
    }
#undef LOAD_FRAGS
#undef DO_MMAS
}

// All three projections in one launch (KV interleaved first, short Q tiles last)
#define N_TILES_X (TEXT_DIM / BN)     // 8
__global__ __launch_bounds__(NT, 2)
void gemm_fp16_all(const __half* __restrict__ Xi,
                   const __half* __restrict__ Bk, const float* __restrict__ bk,
                   __half* __restrict__ Ck,
                   const __half* __restrict__ Bv, const float* __restrict__ bv,
                   __half* __restrict__ Cv,
                   const __half* __restrict__ Xt,
                   const __half* __restrict__ Bq, const float* __restrict__ bq,
                   __half* __restrict__ Cq)
{
    extern __shared__ char smem[];
    const int id = blockIdx.x;

    const __half* A;
    const __half* B;
    const float* bias;
    __half* C;
    int K, m0, n0;

    if (id < 2 * N_TILES_X * (BATCH / BM)) {
        const int proj = id & 1;
        n0 = ((id >> 1) & (N_TILES_X - 1)) * BN;
        m0 = (id >> 4) * BM;
        A = Xi; K = IMAGE_DIM;
        if (proj == 0) { B = Bk; bias = bk; C = Ck; }
        else           { B = Bv; bias = bv; C = Cv; }
    } else {
        const int qid = id - 2 * N_TILES_X * (BATCH / BM);
        n0 = (qid & (N_TILES_X - 1)) * BN;
        m0 = (qid >> 3) * BM;
        A = Xt; K = TEXT_DIM;
        B = Bq; bias = bq; C = Cq;
    }
    gemm_body(A, B, bias, C, K, smem, m0, n0);
}

// ---------------- conversion: 8 floats/thread/iter, 16B stores ----------------
__device__ __forceinline__ void cvt8(const float4* __restrict__ in,
                                     uint4* __restrict__ out, int i)
{
    const float4 va = in[2 * i];
    const float4 vb = in[2 * i + 1];
    uint4 o;
    *(__half2*)&o.x = __floats2half2_rn(va.x, va.y);
    *(__half2*)&o.y = __floats2half2_rn(va.z, va.w);
    *(__half2*)&o.z = __floats2half2_rn(vb.x, vb.y);
    *(__half2*)&o.w = __floats2half2_rn(vb.z, vb.w);
    out[i] = o;
}

__global__ __launch_bounds__(256)
void f32_to_f16_all(const float* __restrict__ i0, __half* __restrict__ o0, int n8_0,
                    const float* __restrict__ i1, __half* __restrict__ o1, int n8_1,
                    const float* __restrict__ i2, __half* __restrict__ o2, int n8_2,
                    const float* __restrict__ i3, __half* __restrict__ o3, int n8_3,
                    const float* __restrict__ i4, __half* __restrict__ o4, int n8_4)
{
    const int stride = gridDim.x * 256;
    const int t0 = blockIdx.x * 256 + threadIdx.x;
    #pragma unroll 1
    for (int i = t0; i < n8_0; i += stride) cvt8((const float4*)i0, (uint4*)o0, i);
    #pragma unroll 1
    for (int i = t0; i < n8_1; i += stride) cvt8((const float4*)i1, (uint4*)o1, i);
    #pragma unroll 1
    for (int i = t0; i < n8_2; i += stride) cvt8((const float4*)i2, (uint4*)o2, i);
    #pragma unroll 1
    for (int i = t0; i < n8_3; i += stride) cvt8((const float4*)i3, (uint4*)o3, i);
    #pragma unroll 1
    for (int i = t0; i < n8_4; i += stride) cvt8((const float4*)i4, (uint4*)o4, i);
}

// ---------------- fused attention + residual + LayerNorm ----------------
// 1 row / 256 threads; K,V kept as __half2 in smem (halved crossbar traffic).
__global__ __launch_bounds__(256)
void attn_ln_kernel(const __half* __restrict__ Qf, const __half* __restrict__ Kf,
                    const __half* __restrict__ Vf, const __half* __restrict__ Xt,
                    const float* __restrict__ gamma, const float* __restrict__ beta,
                    float* __restrict__ out)
{
    __shared__ __half2 sK2[TEXT_DIM / 2];
    __shared__ __half2 sV2[TEXT_DIM / 2];
    __shared__ float   sX[TEXT_DIM];
    __shared__ float   red[8][2];
    __shared__ float   stats[2];

    const int tid  = threadIdx.x;
    const int lane = tid & 31;
    const int h    = tid >> 5;
    const size_t base = (size_t)blockIdx.x * TEXT_DIM;

    {
        const uint2 kv = *(const uint2*)(Kf + base + tid * 4);
        const uint2 vv = *(const uint2*)(Vf + base + tid * 4);
        *(uint2*)(sK2 + tid * 2) = kv;
        *(uint2*)(sV2 + tid * 2) = vv;
    }

    const __half2* qh2 = (const __half2*)(Qf + base + h * HEAD_DIM);
    const float2 q2a = __half22float2(qh2[lane]);
    const float2 q2b = __half22float2(qh2[lane + 32]);
    __syncthreads();

    float s[NUM_HEADS];
    #pragma unroll
    for (int g = 0; g < NUM_HEADS; g++) {
        const __half2* kg = sK2 + g * (HEAD_DIM / 2);
        const float2 k2a = __half22float2(kg[lane]);
        const float2 k2b = __half22float2(kg[lane + 32]);
        float p = q2a.x * k2a.x + q2a.y * k2a.y + q2b.x * k2b.x + q2b.y * k2b.y;
        #pragma unroll
        for (int off = 16; off > 0; off >>= 1)
            p += __shfl_xor_sync(0xffffffffu, p, off);
        s[g] = p * 0.08838834764831845f;
    }
    float mx = s[0];
    #pragma unroll
    for (int g = 1; g < NUM_HEADS; g++) mx = fmaxf(mx, s[g]);
    float sum = 0.f;
    #pragma unroll
    for (int g = 0; g < NUM_HEADS; g++) { s[g] = __expf(s[g] - mx); sum += s[g]; }
    const float isum = 1.f / sum;

    const __half2* trow2 = (const __half2*)(Xt + base + h * HEAD_DIM);
    #pragma unroll
    for (int j = 0; j < 2; j++) {
        const int idx = lane + 32 * j;
        float ax = 0.f, ay = 0.f;
        #pragma unroll
        for (int g = 0; g < NUM_HEADS; g++) {
            const float2 v2 = __half22float2(sV2[g * (HEAD_DIM / 2) + idx]);
            ax += s[g] * v2.x;
            ay += s[g] * v2.y;
        }
        const float2 r2 = __half22float2(trow2[idx]);
        float2 xv2;
        xv2.x = ax * isum + r2.x;
        xv2.y = ay * isum + r2.y;
        *(float2*)(sX + h * HEAD_DIM + 2 * idx) = xv2;
    }
    __syncthreads();

    const float4 xv = *(const float4*)(sX + tid * 4);
    float sm = xv.x + xv.y + xv.z + xv.w;
    float sq = xv.x * xv.x + xv.y * xv.y + xv.z * xv.z + xv.w * xv.w;
    #pragma unroll
    for (int off = 16; off > 0; off >>= 1) {
        sm += __shfl_xor_sync(0xffffffffu, sm, off);
        sq += __shfl_xor_sync(0xffffffffu, sq, off);
    }
    if (lane == 0) { red[h][0] = sm; red[h][1] = sq; }
    __syncthreads();
    if (tid == 0) {
        float S = 0.f, SQ = 0.f;
        #pragma unroll
        for (int w = 0; w < 8; w++) { S += red[w][0]; SQ += red[w][1]; }
        const float mu  = S * (1.f / TEXT_DIM);
        const float var = SQ * (1.f / TEXT_DIM) - mu * mu;
        stats[0] = mu;
        stats[1] = rsqrtf(var + 1e-5f);
    }
    __syncthreads();
    const float mu = stats[0], rstd = stats[1];

    const float4 gv = *(const float4*)(gamma + tid * 4);
    const float4 bv = *(const float4*)(beta  + tid * 4);
    float4 yv;
    yv.x = (xv.x - mu) * rstd * gv.x + bv.x;
    yv.y = (xv.y - mu) * rstd * gv.y + bv.y;
    yv.z = (xv.z - mu) * rstd * gv.z + bv.z;
    yv.w = (xv.w - mu) * rstd * gv.w + bv.w;
    *(float4*)(out + base + tid * 4) = yv;
}

// ---------------- launch (single stream) ----------------
extern "C" void kernel_launch(void* const* d_in, const int* in_sizes, int n_in,
                              void* d_out, int out_size)
{
    const float* text  = (const float*)d_in[0];
    const float* image = (const float*)d_in[1];
    const float* Wq    = (const float*)d_in[2];
    const float* bq    = (const float*)d_in[3];
    const float* Wk    = (const float*)d_in[4];
    const float* bk    = (const float*)d_in[5];
    const float* Wv    = (const float*)d_in[6];
    const float* bv    = (const float*)d_in[7];
    const float* gamma = (const float*)d_in[8];
    const float* beta  = (const float*)d_in[9];
    float* out = (float*)d_out;

    __half *Qh, *Kh, *Vh, *Xt, *Xi, *Wqh, *Wkh, *Wvh;
    cudaGetSymbolAddress((void**)&Qh,  g_Qh);
    cudaGetSymbolAddress((void**)&Kh,  g_Kh);
    cudaGetSymbolAddress((void**)&Vh,  g_Vh);
    cudaGetSymbolAddress((void**)&Xt,  g_Xt);
    cudaGetSymbolAddress((void**)&Xi,  g_Xi);
    cudaGetSymbolAddress((void**)&Wqh, g_Wq);
    cudaGetSymbolAddress((void**)&Wkh, g_Wk);
    cudaGetSymbolAddress((void**)&Wvh, g_Wv);

    cudaFuncSetAttribute(gemm_fp16_all,
                         cudaFuncAttributeMaxDynamicSharedMemorySize, GEMM_SMEM);

    {
        const int n8i = (BATCH * IMAGE_DIM) / 8;
        const int n8t = (BATCH * TEXT_DIM) / 8;
        const int n8k = (TEXT_DIM * IMAGE_DIM) / 8;
        const int n8q = (TEXT_DIM * TEXT_DIM) / 8;
        f32_to_f16_all<<<4096, 256>>>(image, Xi, n8i,
                                      text,  Xt, n8t,
                                      Wk,    Wkh, n8k,
                                      Wv,    Wvh, n8k,
                                      Wq,    Wqh, n8q);
    }

    gemm_fp16_all<<<3072, NT, GEMM_SMEM>>>(Xi, Wkh, bk, Kh, Wvh, bv, Vh,
                                           Xt, Wqh, bq, Qh);

    attn_ln_kernel<<<BATCH, 256>>>(Qh, Kh, Vh, Xt, gamma, beta, out);
}